// round 10
// baseline (speedup 1.0000x reference)
#include <cuda_runtime.h>
#include <cstdint>

// KNRM via warp-level bf16 mma.sync (3-split), D split across 2 CTAs/batch for
// 2-CTA/SM phase overlap. B=128, Q=16, D=1024, E=300, K=11.
#define B_SZ 128
#define Q_SZ 16
#define D_SZ 1024
#define DHALF 512
#define E_SZ 300
#define K_SZ 11
#define MT 64                    // doc rows per tile
#define NTILE 8                  // 8 * 64 = 512 rows per CTA
#define NKS 19                   // k-steps of 16 (covers 304 >= 300)
#define STRB 624                 // row stride bytes (312 bf16; 624=39*16 -> conflict-free ldsm)

// smem byte offsets
#define OFF_AHI  0
#define OFF_ALO  (OFF_AHI + 64 * STRB)      // 39936
#define OFF_BHI  (OFF_ALO + 64 * STRB)      // 79872
#define OFF_BLO  (OFF_BHI + 16 * STRB)      // 89856
#define OFF_RND  (OFF_BLO + 16 * STRB)      // 99840 : 64 floats
#define OFF_RNQ  (OFF_RND + 256)            // 100096 : 16 floats
#define OFF_RED  (OFF_RNQ + 64)             // 100160 : 8 warps x 4 m x 24 floats
#define SMEM_BYTES (OFF_RED + 3072 + 16)    // 103248 -> 2 CTAs/SM

__device__ float g_part[2 * B_SZ * 192];

__device__ __forceinline__ uint32_t smem_u32(const void* p) {
    uint32_t a;
    asm("{ .reg .u64 t; cvta.to.shared.u64 t, %1; cvt.u32.u64 %0, t; }" : "=r"(a) : "l"(p));
    return a;
}
__device__ __forceinline__ float ex2f(float x) {
    float y; asm("ex2.approx.f32 %0, %1;" : "=f"(y) : "f"(x)); return y;
}
__device__ __forceinline__ uint32_t packbf(float lo, float hi) {
    uint32_t r;
    asm("cvt.rn.bf16x2.f32 %0, %1, %2;" : "=r"(r) : "f"(hi), "f"(lo));
    return r;
}
__device__ __forceinline__ void sts64(uint32_t a, uint32_t x, uint32_t y) {
    asm volatile("st.shared.v2.b32 [%0], {%1, %2};" :: "r"(a), "r"(x), "r"(y) : "memory");
}
__device__ __forceinline__ void ldsm4(uint32_t& r0, uint32_t& r1, uint32_t& r2, uint32_t& r3,
                                      uint32_t addr) {
    asm volatile("ldmatrix.sync.aligned.m8n8.x4.shared.b16 {%0,%1,%2,%3}, [%4];"
                 : "=r"(r0), "=r"(r1), "=r"(r2), "=r"(r3) : "r"(addr));
}
__device__ __forceinline__ void ldsm2(uint32_t& r0, uint32_t& r1, uint32_t addr) {
    asm volatile("ldmatrix.sync.aligned.m8n8.x2.shared.b16 {%0,%1}, [%2];"
                 : "=r"(r0), "=r"(r1) : "r"(addr));
}
__device__ __forceinline__ void mma_bf16(float* c, uint32_t a0, uint32_t a1, uint32_t a2,
                                         uint32_t a3, uint32_t b0, uint32_t b1) {
    asm volatile(
        "mma.sync.aligned.m16n8k16.row.col.f32.bf16.bf16.f32 "
        "{%0,%1,%2,%3}, {%4,%5,%6,%7}, {%8,%9}, {%0,%1,%2,%3};"
        : "+f"(c[0]), "+f"(c[1]), "+f"(c[2]), "+f"(c[3])
        : "r"(a0), "r"(a1), "r"(a2), "r"(a3), "r"(b0), "r"(b1));
}

#define REDW(v) { v += __shfl_xor_sync(0xffffffffu, v, 4);  \
                  v += __shfl_xor_sync(0xffffffffu, v, 8);  \
                  v += __shfl_xor_sync(0xffffffffu, v, 16); }

// Convert one float4 (cols 4f..4f+3 of row r) to bf16 hi/lo and store (row-major).
__device__ __forceinline__ void conv_store(float4 v, uint32_t hi_base, uint32_t lo_base,
                                           int r, int f, float& ssq) {
    ssq += v.x * v.x + v.y * v.y + v.z * v.z + v.w * v.w;
    uint32_t h0 = packbf(v.x, v.y);
    uint32_t h1 = packbf(v.z, v.w);
    float fx = __uint_as_float(h0 << 16), fy = __uint_as_float(h0 & 0xffff0000u);
    float fz = __uint_as_float(h1 << 16), fw = __uint_as_float(h1 & 0xffff0000u);
    uint32_t l0 = packbf(v.x - fx, v.y - fy);
    uint32_t l1 = packbf(v.z - fz, v.w - fw);
    uint32_t o = (uint32_t)r * STRB + (uint32_t)f * 8u;
    sts64(hi_base + o, h0, h1);
    sts64(lo_base + o, l0, l1);
}

__global__ void __launch_bounds__(256, 2)
knrm_mma(const int* __restrict__ doctoks, const int* __restrict__ querytoks,
         const float* __restrict__ emb, const float* __restrict__ mus,
         const float* __restrict__ sigmas)
{
    extern __shared__ char smb[];
    const uint32_t sb = smem_u32(smb);
    float* rnd = (float*)(smb + OFF_RND);
    float* rnq = (float*)(smb + OFF_RNQ);
    float* red = (float*)(smb + OFF_RED);

    const int tid = threadIdx.x;
    const int bid = blockIdx.x;
    const int b   = bid >> 1;
    const int h   = bid & 1;
    const int wid = tid >> 5, lane = tid & 31;
    const int* dtoks = doctoks + b * D_SZ + h * DHALF;

    // Zero padding cols 300..311 (24 B at byte offset 600) of all 160 rows.
    if (tid < 160) {
        uint32_t base;
        if (tid < 64)       base = sb + OFF_AHI + tid * STRB;
        else if (tid < 128) base = sb + OFF_ALO + (tid - 64) * STRB;
        else if (tid < 144) base = sb + OFF_BHI + (tid - 128) * STRB;
        else                base = sb + OFF_BLO + (tid - 144) * STRB;
        sts64(base + 600, 0u, 0u);
        sts64(base + 608, 0u, 0u);
        sts64(base + 616, 0u, 0u);
    }

    // ---- Query tile: convert to bf16 hi/lo + inverse norms ----
    {
        int q = tid >> 4, p = tid & 15;
        int tok = querytoks[b * Q_SZ + q];
        const float4* src = (const float4*)(emb + (long)tok * E_SZ);
        float ss = 0.f;
#pragma unroll
        for (int i = 0; i < 5; i++) {
            int f = p + 16 * i;
            if (f < 75)
                conv_store(src[f], sb + OFF_BHI, sb + OFF_BLO, q, f, ss);
        }
        ss += __shfl_xor_sync(0xffffffffu, ss, 1);
        ss += __shfl_xor_sync(0xffffffffu, ss, 2);
        ss += __shfl_xor_sync(0xffffffffu, ss, 4);
        ss += __shfl_xor_sync(0xffffffffu, ss, 8);
        if (p == 0) rnq[q] = 1.f / (sqrtf(ss) + 1e-9f);
    }
    __syncthreads();

    // RBF constants
    const float mu0   = mus[0];
    const float delta = mus[1] - mus[0];
    float sg = sigmas[0];
    const float c2a = -0.72134752044448169f / (sg * sg);
    const float mu10 = mus[10];
    sg = sigmas[10];
    const float c2b = -0.72134752044448169f / (sg * sg);

    // warp = rg*2 + nh: rg picks 16 doc rows, nh picks 8 q cols
    const int rg = wid >> 1;
    const int nh = wid & 1;
    const uint32_t lrow = lane & 15;
    const uint32_t lkof = (uint32_t)(lane >> 4) * 16u;       // A: k offset 0/8 cols
    const uint32_t aAH = sb + OFF_AHI + (16 * rg + lrow) * STRB + lkof;
    const uint32_t aAL = sb + OFF_ALO + (16 * rg + lrow) * STRB + lkof;
    // B (x2): lanes 0-15 -> q rows nh*8 + (lane&7), k offset 0/8
    const uint32_t brow = (uint32_t)(nh * 8) + (lane & 7);
    const uint32_t bkof = (uint32_t)((lane >> 3) & 1) * 16u;
    const uint32_t aBH = sb + OFF_BHI + brow * STRB + bkof;
    const uint32_t aBL = sb + OFF_BLO + brow * STRB + bkof;

    // sim coordinates: rows r0/r1, q cols q0/q1
    const int m  = lane & 3;
    const int r0 = 16 * rg + (lane >> 2);
    const int r1 = r0 + 8;
    const int q0 = nh * 8 + 2 * m;
    const float rq0 = rnq[q0], rq1 = rnq[q0 + 1];

    float kq[2][K_SZ], ssim[2];
#pragma unroll
    for (int j = 0; j < 2; j++) {
        ssim[j] = 0.f;
#pragma unroll
        for (int k = 0; k < K_SZ; k++) kq[j][k] = 0.f;
    }

    for (int c = 0; c < NTILE; c++) {
        // ---- gather + convert 64 doc rows (4 threads per row) ----
        {
            int rt = tid >> 2, p = tid & 3;
            int tok = dtoks[c * MT + rt];
            const float4* src = (const float4*)(emb + (long)tok * E_SZ);
            float ss = 0.f;
#pragma unroll
            for (int i = 0; i < 19; i++) {
                int f = p + 4 * i;
                if (f < 75)
                    conv_store(src[f], sb + OFF_AHI, sb + OFF_ALO, rt, f, ss);
            }
            ss += __shfl_xor_sync(0xffffffffu, ss, 1);
            ss += __shfl_xor_sync(0xffffffffu, ss, 2);
            if (p == 0) rnd[rt] = 1.f / (sqrtf(ss) + 1e-9f);
        }
        __syncthreads();

        // ---- MMA: 19 k-steps, 3 split-passes, one 16x8 C block per warp ----
        float acc[4];
#pragma unroll
        for (int i = 0; i < 4; i++) acc[i] = 0.f;

#pragma unroll
        for (int ks = 0; ks < NKS; ks++) {
            uint32_t ko = (uint32_t)ks * 32u;
            uint32_t ah0, ah1, ah2, ah3, al0, al1, al2, al3;
            uint32_t bh0, bh1, bl0, bl1;
            ldsm4(ah0, ah1, ah2, ah3, aAH + ko);
            ldsm4(al0, al1, al2, al3, aAL + ko);
            ldsm2(bh0, bh1, aBH + ko);
            ldsm2(bl0, bl1, aBL + ko);
            mma_bf16(acc, ah0, ah1, ah2, ah3, bh0, bh1);   // hi*hi
            mma_bf16(acc, ah0, ah1, ah2, ah3, bl0, bl1);   // hi*lo
            mma_bf16(acc, al0, al1, al2, al3, bh0, bh1);   // lo*hi
        }

        // ---- normalize + RBF (sims in registers) ----
        float rd0 = rnd[r0], rd1 = rnd[r1];
        float sv[4];
        sv[0] = acc[0] * rd0 * rq0;
        sv[1] = acc[1] * rd0 * rq1;
        sv[2] = acc[2] * rd1 * rq0;
        sv[3] = acc[3] * rd1 * rq1;
#pragma unroll
        for (int i = 0; i < 4; i++) {
            int j = i & 1;
            float s = sv[i];
            ssim[j] += s;
            float tt = s - mu0;
#pragma unroll
            for (int k = 0; k < 10; k++) {
                kq[j][k] += ex2f(c2a * tt * tt);
                tt -= delta;
            }
            tt = s - mu10;
            kq[j][10] += ex2f(c2b * tt * tt);
        }
        __syncthreads();    // before next tile overwrites A / rnd
    }

    // ---- reduce: in-warp over lane bits 2-4 (rows), cross-warp over rg via smem ----
#pragma unroll
    for (int j = 0; j < 2; j++) {
        REDW(ssim[j]);
#pragma unroll
        for (int k = 0; k < K_SZ; k++) REDW(kq[j][k]);
    }
    if (lane < 4) {
        float* r = red + wid * 96 + lane * 24;     // lane == m here
#pragma unroll
        for (int j = 0; j < 2; j++) {
#pragma unroll
            for (int k = 0; k < K_SZ; k++) r[j * 12 + k] = kq[j][k];
            r[j * 12 + 11] = ssim[j];
        }
    }
    __syncthreads();
    if (tid < Q_SZ * 12) {
        int q = tid / 12, v = tid - q * 12;
        int nhq = q >> 3, mq = (q & 7) >> 1, j = q & 1;
        float sum = 0.f;
#pragma unroll
        for (int rgi = 0; rgi < 4; rgi++)
            sum += red[(2 * rgi + nhq) * 96 + mq * 24 + j * 12 + v];
        g_part[bid * 192 + tid] = sum;
    }
}

// Combine the two D-halves, apply mask/log, Q-sum, FC head.
__global__ void knrm_final(const float* __restrict__ fcw,
                           const float* __restrict__ fcb,
                           float* __restrict__ out)
{
    __shared__ float qf[192];
    const int b = blockIdx.x;
    const int tid = threadIdx.x;
    if (tid < 192)
        qf[tid] = g_part[(2 * b) * 192 + tid] + g_part[(2 * b + 1) * 192 + tid];
    __syncthreads();

    float partial = 0.f;
    if (tid < K_SZ) {
        float acc = 0.f;
        for (int q = 0; q < Q_SZ; q++)
            if (qf[q * 12 + 11] != 0.0f)
                acc += logf(qf[q * 12 + tid] + 1e-6f);
        partial = acc * fcw[tid];
    }
    if (tid < 32) {
#pragma unroll
        for (int mm = 16; mm; mm >>= 1)
            partial += __shfl_xor_sync(0xffffffffu, partial, mm);
        if (tid == 0) out[b] = partial + fcb[0];
    }
}

extern "C" void kernel_launch(void* const* d_in, const int* in_sizes, int n_in,
                              void* d_out, int out_size)
{
    const int*   doctoks   = (const int*)d_in[0];
    const int*   querytoks = (const int*)d_in[1];
    // d_in[2] = query_idf (unused by the reference)
    const float* emb       = (const float*)d_in[3];
    const float* mus       = (const float*)d_in[4];
    const float* sigmas    = (const float*)d_in[5];
    const float* fc_w      = (const float*)d_in[6];
    const float* fc_b      = (const float*)d_in[7];
    float* out = (float*)d_out;

    cudaFuncSetAttribute(knrm_mma, cudaFuncAttributeMaxDynamicSharedMemorySize, SMEM_BYTES);
    knrm_mma<<<2 * B_SZ, 256, SMEM_BYTES>>>(doctoks, querytoks, emb, mus, sigmas);
    knrm_final<<<B_SZ, 192>>>(fc_w, fc_b, out);
}

// round 11
// speedup vs baseline: 1.1012x; 1.1012x over previous
#include <cuda_runtime.h>
#include <cstdint>

// KNRM: mma.sync bf16 3-split + cp.async raw staging + register-side conversion.
// B=128, Q=16, D=1024, E=300, K=11. Grid 128, 256 threads, 1 CTA/SM.
#define B_SZ 128
#define Q_SZ 16
#define D_SZ 1024
#define E_SZ 300
#define K_SZ 11
#define MT 64                    // doc rows per tile
#define NTILE 16
#define NKS 19                   // k-steps of 16 (covers 304 >= 300)
#define RSTR_B 1312              // raw fp32 row stride bytes (328 floats; 1312 % 128 == 32)
#define RAW_BYTES (64 * RSTR_B)  // 83968 per buffer
#define STRB 624                 // B bf16 row stride bytes (312 cols)

#define OFF_RAW0 0
#define OFF_RAW1 (OFF_RAW0 + RAW_BYTES)      // 83968
#define OFF_BHI  (OFF_RAW1 + RAW_BYTES)      // 167936
#define OFF_BLO  (OFF_BHI + 16 * STRB)       // 177920
#define OFF_RNQ  (OFF_BLO + 16 * STRB)       // 187904 : 16 floats
#define OFF_RED  (OFF_RNQ + 64)              // 187968 : 8 warps x 4 m x 24 floats
#define OFF_QFIN (OFF_RED + 3072)            // 191040 : 192 floats
#define SMEM_BYTES (OFF_QFIN + 768 + 16)     // 191824 -> 1 CTA/SM

__device__ __forceinline__ uint32_t smem_u32(const void* p) {
    uint32_t a;
    asm("{ .reg .u64 t; cvta.to.shared.u64 t, %1; cvt.u32.u64 %0, t; }" : "=r"(a) : "l"(p));
    return a;
}
__device__ __forceinline__ float ex2f(float x) {
    float y; asm("ex2.approx.f32 %0, %1;" : "=f"(y) : "f"(x)); return y;
}
__device__ __forceinline__ uint32_t packbf(float lo, float hi) {
    uint32_t r;
    asm("cvt.rn.bf16x2.f32 %0, %1, %2;" : "=r"(r) : "f"(hi), "f"(lo));
    return r;
}
__device__ __forceinline__ void sts64(uint32_t a, uint32_t x, uint32_t y) {
    asm volatile("st.shared.v2.b32 [%0], {%1, %2};" :: "r"(a), "r"(x), "r"(y) : "memory");
}
__device__ __forceinline__ float2 lds64(uint32_t a) {
    float2 v;
    asm volatile("ld.shared.v2.f32 {%0,%1}, [%2];" : "=f"(v.x), "=f"(v.y) : "r"(a));
    return v;
}
__device__ __forceinline__ void ldsm2(uint32_t& r0, uint32_t& r1, uint32_t addr) {
    asm volatile("ldmatrix.sync.aligned.m8n8.x2.shared.b16 {%0,%1}, [%2];"
                 : "=r"(r0), "=r"(r1) : "r"(addr));
}
__device__ __forceinline__ void mma_bf16(float* c, uint32_t a0, uint32_t a1, uint32_t a2,
                                         uint32_t a3, uint32_t b0, uint32_t b1) {
    asm volatile(
        "mma.sync.aligned.m16n8k16.row.col.f32.bf16.bf16.f32 "
        "{%0,%1,%2,%3}, {%4,%5,%6,%7}, {%8,%9}, {%0,%1,%2,%3};"
        : "+f"(c[0]), "+f"(c[1]), "+f"(c[2]), "+f"(c[3])
        : "r"(a0), "r"(a1), "r"(a2), "r"(a3), "r"(b0), "r"(b1));
}
__device__ __forceinline__ void cp_async16(uint32_t dst, const float* src) {
    asm volatile("cp.async.cg.shared.global [%0], [%1], 16;" :: "r"(dst), "l"(src));
}
#define CP_COMMIT() asm volatile("cp.async.commit_group;")
#define CP_WAIT1()  asm volatile("cp.async.wait_group 1;")

#define REDW(v) { v += __shfl_xor_sync(0xffffffffu, v, 4);  \
                  v += __shfl_xor_sync(0xffffffffu, v, 8);  \
                  v += __shfl_xor_sync(0xffffffffu, v, 16); }

// fp32 pair -> bf16 hi pack + lo pack (lo = x - float(bf16(x)))
__device__ __forceinline__ void cvt2(float2 v, uint32_t& hi, uint32_t& lo) {
    hi = packbf(v.x, v.y);
    float hx = __uint_as_float(hi << 16);
    float hy = __uint_as_float(hi & 0xffff0000u);
    lo = packbf(v.x - hx, v.y - hy);
}

// Q-side conversion into bf16 hi/lo smem (row-major, stride STRB).
__device__ __forceinline__ void conv_store(float4 v, uint32_t hi_base, uint32_t lo_base,
                                           int r, int f, float& ssq) {
    ssq += v.x * v.x + v.y * v.y + v.z * v.z + v.w * v.w;
    uint32_t h0 = packbf(v.x, v.y);
    uint32_t h1 = packbf(v.z, v.w);
    float fx = __uint_as_float(h0 << 16), fy = __uint_as_float(h0 & 0xffff0000u);
    float fz = __uint_as_float(h1 << 16), fw = __uint_as_float(h1 & 0xffff0000u);
    uint32_t l0 = packbf(v.x - fx, v.y - fy);
    uint32_t l1 = packbf(v.z - fz, v.w - fw);
    uint32_t o = (uint32_t)r * STRB + (uint32_t)f * 8u;
    sts64(hi_base + o, h0, h1);
    sts64(lo_base + o, l0, l1);
}

// Async gather of one 64-row raw fp32 tile (4 threads per row).
__device__ __forceinline__ void prefetch_raw(const int* __restrict__ toks,
                                             const float* __restrict__ emb,
                                             uint32_t rawbase, int tid)
{
    int rt = tid >> 2, p = tid & 3;
    long tok = toks[rt];
    const float* src = emb + tok * (long)E_SZ;
    uint32_t dst = rawbase + (uint32_t)rt * RSTR_B;
#pragma unroll
    for (int i = 0; i < 19; i++) {
        int f = p + 4 * i;
        if (f < 75) cp_async16(dst + (uint32_t)f * 16u, src + f * 4);
    }
}

__global__ void __launch_bounds__(256, 1)
knrm_mma(const int* __restrict__ doctoks, const int* __restrict__ querytoks,
         const float* __restrict__ emb, const float* __restrict__ mus,
         const float* __restrict__ sigmas, const float* __restrict__ fcw,
         const float* __restrict__ fcb, float* __restrict__ out)
{
    extern __shared__ char smb[];
    const uint32_t sb = smem_u32(smb);
    float* rnq  = (float*)(smb + OFF_RNQ);
    float* red  = (float*)(smb + OFF_RED);
    float* qfin = (float*)(smb + OFF_QFIN);

    const int tid = threadIdx.x;
    const int b   = blockIdx.x;
    const int wid = tid >> 5, lane = tid & 31;
    const int* dtoks = doctoks + b * D_SZ;

    // Kick off async gather of tiles 0 and 1.
    prefetch_raw(dtoks, emb, sb + OFF_RAW0, tid);
    CP_COMMIT();
    prefetch_raw(dtoks + MT, emb, sb + OFF_RAW1, tid);
    CP_COMMIT();

    // Zero raw padding cols 300..327 (bytes 1200..1311) of all 128 rows (both buffers).
    for (int i = tid; i < 128 * 7; i += 256) {
        int r = i / 7, p = i - r * 7;
        sts64(sb + OFF_RAW0 + (uint32_t)r * RSTR_B + 1200u + (uint32_t)p * 16u, 0u, 0u);
        sts64(sb + OFF_RAW0 + (uint32_t)r * RSTR_B + 1208u + (uint32_t)p * 16u, 0u, 0u);
    }
    // Zero B padding cols 300..311 (bytes 600..623) of 32 B-rows.
    if (tid < 32) {
        uint32_t base = sb + ((tid < 16) ? OFF_BHI : OFF_BLO) + (uint32_t)(tid & 15) * STRB;
        sts64(base + 600, 0u, 0u);
        sts64(base + 608, 0u, 0u);
        sts64(base + 616, 0u, 0u);
    }

    // ---- Query tile: convert to bf16 hi/lo + inverse norms ----
    {
        int q = tid >> 4, p = tid & 15;
        int tok = querytoks[b * Q_SZ + q];
        const float4* src = (const float4*)(emb + (long)tok * E_SZ);
        float ss = 0.f;
#pragma unroll
        for (int i = 0; i < 5; i++) {
            int f = p + 16 * i;
            if (f < 75)
                conv_store(src[f], sb + OFF_BHI, sb + OFF_BLO, q, f, ss);
        }
        ss += __shfl_xor_sync(0xffffffffu, ss, 1);
        ss += __shfl_xor_sync(0xffffffffu, ss, 2);
        ss += __shfl_xor_sync(0xffffffffu, ss, 4);
        ss += __shfl_xor_sync(0xffffffffu, ss, 8);
        if (p == 0) rnq[q] = 1.f / (sqrtf(ss) + 1e-9f);
    }
    __syncthreads();

    // RBF constants
    const float mu0   = mus[0];
    const float delta = mus[1] - mus[0];
    float sg = sigmas[0];
    const float c2a = -0.72134752044448169f / (sg * sg);
    const float mu10 = mus[10];
    sg = sigmas[10];
    const float c2b = -0.72134752044448169f / (sg * sg);

    // warp = rg*2 + nh: rg picks 16 doc rows, nh picks 8 q cols
    const int rg = wid >> 1;
    const int nh = wid & 1;
    const int g  = lane >> 2;         // fragment row within 16 (and +8)
    const int t  = lane & 3;          // fragment col pair
    // raw A addresses (relative to raw buffer base)
    const uint32_t r0off = (uint32_t)(16 * rg + g) * RSTR_B + (uint32_t)t * 8u;
    const uint32_t r1off = r0off + 8u * RSTR_B;
    // B ldsm addressing (lanes 0-15 meaningful)
    const uint32_t brow = (uint32_t)(nh * 8) + (lane & 7);
    const uint32_t bkof = (uint32_t)((lane >> 3) & 1) * 16u;
    const uint32_t aBH = sb + OFF_BHI + brow * STRB + bkof;
    const uint32_t aBL = sb + OFF_BLO + brow * STRB + bkof;

    const int q0 = nh * 8 + 2 * t;
    const float rq0 = rnq[q0], rq1 = rnq[q0 + 1];

    float kq[2][K_SZ], ssim[2];
#pragma unroll
    for (int j = 0; j < 2; j++) {
        ssim[j] = 0.f;
#pragma unroll
        for (int k = 0; k < K_SZ; k++) kq[j][k] = 0.f;
    }

    for (int c = 0; c < NTILE; c++) {
        CP_WAIT1();                 // raw tile c resident
        __syncthreads();
        const uint32_t raw = sb + ((c & 1) ? OFF_RAW1 : OFF_RAW0);
        const uint32_t a00 = raw + r0off;        // row g,   cols 2t..2t+1
        const uint32_t a01 = a00 + 32u;          // row g,   cols 2t+8..2t+9
        const uint32_t a10 = raw + r1off;        // row g+8
        const uint32_t a11 = a10 + 32u;

        float accH[4] = {0.f, 0.f, 0.f, 0.f};    // hi*hi
        float accM[4] = {0.f, 0.f, 0.f, 0.f};    // hi*lo
        float accL[4] = {0.f, 0.f, 0.f, 0.f};    // lo*hi
        float ssq0 = 0.f, ssq1 = 0.f;

#pragma unroll
        for (int ks = 0; ks < NKS; ks++) {
            uint32_t ko = (uint32_t)ks * 64u;    // 16 fp32 cols
            float2 v00 = lds64(a00 + ko);
            float2 v10 = lds64(a10 + ko);
            float2 v01 = lds64(a01 + ko);
            float2 v11 = lds64(a11 + ko);
            ssq0 += v00.x * v00.x + v00.y * v00.y + v01.x * v01.x + v01.y * v01.y;
            ssq1 += v10.x * v10.x + v10.y * v10.y + v11.x * v11.x + v11.y * v11.y;
            uint32_t ah0, al0, ah1, al1, ah2, al2, ah3, al3;
            cvt2(v00, ah0, al0);
            cvt2(v10, ah1, al1);
            cvt2(v01, ah2, al2);
            cvt2(v11, ah3, al3);
            uint32_t bh0, bh1, bl0, bl1;
            ldsm2(bh0, bh1, aBH + (uint32_t)ks * 32u);
            ldsm2(bl0, bl1, aBL + (uint32_t)ks * 32u);
            mma_bf16(accH, ah0, ah1, ah2, ah3, bh0, bh1);
            mma_bf16(accM, ah0, ah1, ah2, ah3, bl0, bl1);
            mma_bf16(accL, al0, al1, al2, al3, bh0, bh1);
        }

        __syncthreads();            // raw tile c consumed by all warps
        if (c + 2 < NTILE)
            prefetch_raw(dtoks + (c + 2) * MT, emb, raw, tid);
        CP_COMMIT();                // keep wait_group counts aligned

        // doc norms from in-register ssq (butterfly over t bits)
        ssq0 += __shfl_xor_sync(0xffffffffu, ssq0, 1);
        ssq0 += __shfl_xor_sync(0xffffffffu, ssq0, 2);
        ssq1 += __shfl_xor_sync(0xffffffffu, ssq1, 1);
        ssq1 += __shfl_xor_sync(0xffffffffu, ssq1, 2);
        float rd0 = 1.f / (sqrtf(ssq0) + 1e-9f);
        float rd1 = 1.f / (sqrtf(ssq1) + 1e-9f);

        // ---- normalize + RBF ----
        float sv[4];
        sv[0] = (accH[0] + accM[0] + accL[0]) * rd0 * rq0;
        sv[1] = (accH[1] + accM[1] + accL[1]) * rd0 * rq1;
        sv[2] = (accH[2] + accM[2] + accL[2]) * rd1 * rq0;
        sv[3] = (accH[3] + accM[3] + accL[3]) * rd1 * rq1;
#pragma unroll
        for (int i = 0; i < 4; i++) {
            int j = i & 1;
            float s = sv[i];
            ssim[j] += s;
            float tt = s - mu0;
#pragma unroll
            for (int k = 0; k < 10; k++) {
                kq[j][k] += ex2f(c2a * tt * tt);
                tt -= delta;
            }
            tt = s - mu10;
            kq[j][10] += ex2f(c2b * tt * tt);
        }
    }

    // ---- reduce: in-warp over g bits, cross-warp over rg via smem ----
#pragma unroll
    for (int j = 0; j < 2; j++) {
        REDW(ssim[j]);
#pragma unroll
        for (int k = 0; k < K_SZ; k++) REDW(kq[j][k]);
    }
    if (lane < 4) {
        float* r = red + wid * 96 + lane * 24;   // lane == t == m
#pragma unroll
        for (int j = 0; j < 2; j++) {
#pragma unroll
            for (int k = 0; k < K_SZ; k++) r[j * 12 + k] = kq[j][k];
            r[j * 12 + 11] = ssim[j];
        }
    }
    __syncthreads();
    if (tid < Q_SZ * 12) {
        int q = tid / 12, v = tid - q * 12;
        int nhq = q >> 3, mq = (q & 7) >> 1, j = q & 1;
        float sum = 0.f;
#pragma unroll
        for (int rgi = 0; rgi < 4; rgi++)
            sum += red[(2 * rgi + nhq) * 96 + mq * 24 + j * 12 + v];
        qfin[q * 12 + v] = sum;
    }
    __syncthreads();

    // ---- log, mask, Q-sum, FC head ----
    float partial = 0.f;
    if (tid < K_SZ) {
        float acc2 = 0.f;
        for (int q = 0; q < Q_SZ; q++)
            if (qfin[q * 12 + 11] != 0.0f)
                acc2 += logf(qfin[q * 12 + tid] + 1e-6f);
        partial = acc2 * fcw[tid];
    }
    if (tid < 32) {
#pragma unroll
        for (int mm = 16; mm; mm >>= 1)
            partial += __shfl_xor_sync(0xffffffffu, partial, mm);
        if (tid == 0) out[b] = partial + fcb[0];
    }
}

extern "C" void kernel_launch(void* const* d_in, const int* in_sizes, int n_in,
                              void* d_out, int out_size)
{
    const int*   doctoks   = (const int*)d_in[0];
    const int*   querytoks = (const int*)d_in[1];
    // d_in[2] = query_idf (unused by the reference)
    const float* emb       = (const float*)d_in[3];
    const float* mus       = (const float*)d_in[4];
    const float* sigmas    = (const float*)d_in[5];
    const float* fc_w      = (const float*)d_in[6];
    const float* fc_b      = (const float*)d_in[7];
    float* out = (float*)d_out;

    cudaFuncSetAttribute(knrm_mma, cudaFuncAttributeMaxDynamicSharedMemorySize, SMEM_BYTES);
    knrm_mma<<<B_SZ, 256, SMEM_BYTES>>>(doctoks, querytoks, emb, mus, sigmas,
                                        fc_w, fc_b, out);
}